// round 1
// baseline (speedup 1.0000x reference)
#include <cuda_runtime.h>
#include <math.h>

// Problem constants
#define BB 4
#define SS 4096
#define DD 1024

// Scratch (device globals; allocation in kernel_launch is forbidden)
__device__ float g_Q[(size_t)BB * SS * DD];      // 64 MB
__device__ float g_K[(size_t)BB * SS * DD];      // 64 MB
__device__ float g_V[(size_t)BB * SS * DD];      // 64 MB
__device__ float g_S[(size_t)BB * SS * SS];      // 256 MB (scores / exp(scores))
__device__ float g_rsum[(size_t)BB * SS];        // per-row softmax sums

// ---------------------------------------------------------------------------
// Tiled fp32 GEMM: C = alpha * A * op(B), optionally row-scaled by 1/rowSum.
//   A: [M,K] row-major
//   B: TB ? [N,K] row-major (NT)  :  [K,N] row-major (NN)
//   C: [M,N] row-major
// Block tile 128x128, K-tile 16, 256 threads, 8x8 per thread, double-buffered.
// All dims must be multiples of the tile sizes (true for this problem).
// ---------------------------------------------------------------------------
#define BM 128
#define BN 128
#define BKT 16
#define TM 8
#define TN 8
#define PAD 4
#define LDAS (BM + PAD)
#define LDBS (BN + PAD)

template <bool TB>
__global__ __launch_bounds__(256, 2)
void gemm_kernel(const float* __restrict__ Ag, const float* __restrict__ Bg,
                 float* __restrict__ Cg,
                 int M, int N, int K,
                 size_t sA, size_t sB, size_t sC,
                 float alpha,
                 const float* __restrict__ rowSum, int rsStride)
{
    __shared__ float As[2][BKT][LDAS];
    __shared__ float Bs[2][BKT][LDBS];

    const float* A = Ag + (size_t)blockIdx.z * sA;
    const float* Bp = Bg + (size_t)blockIdx.z * sB;
    float* C = Cg + (size_t)blockIdx.z * sC;

    const int m0 = blockIdx.y * BM;
    const int n0 = blockIdx.x * BN;
    const int tid = threadIdx.x;

    const int rm = (tid >> 4) * TM;   // 0..120
    const int rn = (tid & 15) * TN;   // 0..120

    // A-style loader indices (also used for B in NT mode)
    const int aRow = tid >> 2;            // 0..63
    const int aC = (tid & 3) << 2;        // 0,4,8,12
    // NN B loader indices
    const int bRow = tid >> 5;            // 0..7
    const int bC = (tid & 31) << 2;       // 0..124

    float acc[TM][TN];
#pragma unroll
    for (int i = 0; i < TM; ++i)
#pragma unroll
        for (int j = 0; j < TN; ++j) acc[i][j] = 0.f;

    const int numT = K / BKT;

    float4 ra0, ra1, rb0, rb1;

    auto gload = [&](int t) {
        const int k0 = t * BKT;
        ra0 = *reinterpret_cast<const float4*>(A + (size_t)(m0 + aRow) * K + k0 + aC);
        ra1 = *reinterpret_cast<const float4*>(A + (size_t)(m0 + aRow + 64) * K + k0 + aC);
        if (TB) {
            rb0 = *reinterpret_cast<const float4*>(Bp + (size_t)(n0 + aRow) * K + k0 + aC);
            rb1 = *reinterpret_cast<const float4*>(Bp + (size_t)(n0 + aRow + 64) * K + k0 + aC);
        } else {
            rb0 = *reinterpret_cast<const float4*>(Bp + (size_t)(k0 + bRow) * N + n0 + bC);
            rb1 = *reinterpret_cast<const float4*>(Bp + (size_t)(k0 + bRow + 8) * N + n0 + bC);
        }
    };

    auto sstore = [&](int buf) {
        As[buf][aC + 0][aRow] = ra0.x;
        As[buf][aC + 1][aRow] = ra0.y;
        As[buf][aC + 2][aRow] = ra0.z;
        As[buf][aC + 3][aRow] = ra0.w;
        As[buf][aC + 0][aRow + 64] = ra1.x;
        As[buf][aC + 1][aRow + 64] = ra1.y;
        As[buf][aC + 2][aRow + 64] = ra1.z;
        As[buf][aC + 3][aRow + 64] = ra1.w;
        if (TB) {
            Bs[buf][aC + 0][aRow] = rb0.x;
            Bs[buf][aC + 1][aRow] = rb0.y;
            Bs[buf][aC + 2][aRow] = rb0.z;
            Bs[buf][aC + 3][aRow] = rb0.w;
            Bs[buf][aC + 0][aRow + 64] = rb1.x;
            Bs[buf][aC + 1][aRow + 64] = rb1.y;
            Bs[buf][aC + 2][aRow + 64] = rb1.z;
            Bs[buf][aC + 3][aRow + 64] = rb1.w;
        } else {
            *reinterpret_cast<float4*>(&Bs[buf][bRow][bC]) = rb0;
            *reinterpret_cast<float4*>(&Bs[buf][bRow + 8][bC]) = rb1;
        }
    };

    gload(0);
    sstore(0);
    __syncthreads();

    for (int t = 0; t < numT; ++t) {
        const int buf = t & 1;
        if (t + 1 < numT) gload(t + 1);

#pragma unroll
        for (int k = 0; k < BKT; ++k) {
            float a[TM], b[TN];
#pragma unroll
            for (int i = 0; i < TM; i += 4) {
                float4 v = *reinterpret_cast<const float4*>(&As[buf][k][rm + i]);
                a[i] = v.x; a[i + 1] = v.y; a[i + 2] = v.z; a[i + 3] = v.w;
            }
#pragma unroll
            for (int j = 0; j < TN; j += 4) {
                float4 v = *reinterpret_cast<const float4*>(&Bs[buf][k][rn + j]);
                b[j] = v.x; b[j + 1] = v.y; b[j + 2] = v.z; b[j + 3] = v.w;
            }
#pragma unroll
            for (int i = 0; i < TM; ++i)
#pragma unroll
                for (int j = 0; j < TN; ++j)
                    acc[i][j] = fmaf(a[i], b[j], acc[i][j]);
        }

        if (t + 1 < numT) sstore(buf ^ 1);
        __syncthreads();
    }

    const float* rs = rowSum ? (rowSum + (size_t)blockIdx.z * rsStride) : nullptr;

#pragma unroll
    for (int i = 0; i < TM; ++i) {
        float sc = alpha;
        if (rs) sc = alpha / rs[m0 + rm + i];
        float* cp = C + (size_t)(m0 + rm + i) * N + n0 + rn;
#pragma unroll
        for (int j = 0; j < TN; j += 4) {
            float4 v;
            v.x = sc * acc[i][j];
            v.y = sc * acc[i][j + 1];
            v.z = sc * acc[i][j + 2];
            v.w = sc * acc[i][j + 3];
            *reinterpret_cast<float4*>(cp + j) = v;
        }
    }
}

// ---------------------------------------------------------------------------
// Row softmax (unnormalized): row <- exp(row - max(row)); rsum[row] = sum.
// Normalization is folded into the PV GEMM epilogue.
// ---------------------------------------------------------------------------
__global__ __launch_bounds__(256)
void softmax_kernel(float* __restrict__ S, float* __restrict__ rsum, int ncols)
{
    float* row = S + (size_t)blockIdx.x * ncols;
    float4* row4 = reinterpret_cast<float4*>(row);
    const int n4 = ncols >> 2;
    const int tid = threadIdx.x;
    __shared__ float red[8];

    float m = -1e30f;
    for (int i = tid; i < n4; i += 256) {
        float4 v = row4[i];
        m = fmaxf(m, fmaxf(fmaxf(v.x, v.y), fmaxf(v.z, v.w)));
    }
#pragma unroll
    for (int o = 16; o > 0; o >>= 1) m = fmaxf(m, __shfl_xor_sync(0xffffffffu, m, o));
    if ((tid & 31) == 0) red[tid >> 5] = m;
    __syncthreads();
    if (tid < 32) {
        float v = (tid < 8) ? red[tid] : -1e30f;
#pragma unroll
        for (int o = 4; o > 0; o >>= 1) v = fmaxf(v, __shfl_xor_sync(0xffffffffu, v, o));
        if (tid == 0) red[0] = v;
    }
    __syncthreads();
    const float mx = red[0];
    __syncthreads();  // everyone has read red[0] before it is reused below

    float s = 0.f;
    for (int i = tid; i < n4; i += 256) {
        float4 v = row4[i];
        v.x = expf(v.x - mx);
        v.y = expf(v.y - mx);
        v.z = expf(v.z - mx);
        v.w = expf(v.w - mx);
        s += v.x + v.y + v.z + v.w;
        row4[i] = v;
    }
#pragma unroll
    for (int o = 16; o > 0; o >>= 1) s += __shfl_xor_sync(0xffffffffu, s, o);
    if ((tid & 31) == 0) red[tid >> 5] = s;
    __syncthreads();
    if (tid == 0) {
        float v = 0.f;
#pragma unroll
        for (int w = 0; w < 8; ++w) v += red[w];
        rsum[blockIdx.x] = v;
    }
}

// ---------------------------------------------------------------------------
// Launch
// ---------------------------------------------------------------------------
extern "C" void kernel_launch(void* const* d_in, const int* in_sizes, int n_in,
                              void* d_out, int out_size)
{
    const float* x  = (const float*)d_in[0];
    const float* Wq = (const float*)d_in[1];
    const float* Wk = (const float*)d_in[2];
    const float* Wv = (const float*)d_in[3];
    float* out = (float*)d_out;

    float *pQ, *pK, *pV, *pS, *pR;
    cudaGetSymbolAddress((void**)&pQ, g_Q);
    cudaGetSymbolAddress((void**)&pK, g_K);
    cudaGetSymbolAddress((void**)&pV, g_V);
    cudaGetSymbolAddress((void**)&pS, g_S);
    cudaGetSymbolAddress((void**)&pR, g_rsum);

    const int M_proj = BB * SS;     // 16384
    const float scale = 1.0f / 32.0f;  // 1/sqrt(1024)

    // Phase 1: projections  Q/K/V = X @ W  (NN, M=16384, N=1024, K=1024)
    {
        dim3 grid(DD / BN, M_proj / BM, 1);
        gemm_kernel<false><<<grid, 256>>>(x, Wq, pQ, M_proj, DD, DD, 0, 0, 0, 1.0f, nullptr, 0);
        gemm_kernel<false><<<grid, 256>>>(x, Wk, pK, M_proj, DD, DD, 0, 0, 0, 1.0f, nullptr, 0);
        gemm_kernel<false><<<grid, 256>>>(x, Wv, pV, M_proj, DD, DD, 0, 0, 0, 1.0f, nullptr, 0);
    }

    // Phase 2: scores = scale * Q @ K^T  (NT, per batch, M=N=4096, K=1024)
    {
        dim3 grid(SS / BN, SS / BM, BB);
        gemm_kernel<true><<<grid, 256>>>(pQ, pK, pS, SS, SS, DD,
                                         (size_t)SS * DD, (size_t)SS * DD, (size_t)SS * SS,
                                         scale, nullptr, 0);
    }

    // Phase 3: row softmax (unnormalized exp + row sums)
    softmax_kernel<<<BB * SS, 256>>>(pS, pR, SS);

    // Phase 4: out = (expS @ V) / rowsum  (NN, per batch, M=4096, N=1024, K=4096)
    {
        dim3 grid(DD / BN, SS / BM, BB);
        gemm_kernel<false><<<grid, 256>>>(pS, pV, out, SS, DD, SS,
                                          (size_t)SS * SS, (size_t)SS * DD, (size_t)SS * DD,
                                          1.0f, pR, SS);
    }
}

// round 3
// speedup vs baseline: 2.7036x; 2.7036x over previous
#include <cuda_runtime.h>
#include <cuda_bf16.h>
#include <stdint.h>
#include <math.h>

#define BB 4
#define SS 4096
#define DD 1024
#define MPROJ (BB*SS)

// ---------------- device scratch ----------------
__device__ __nv_bfloat16 g_xh[(size_t)MPROJ*DD], g_xl[(size_t)MPROJ*DD];
__device__ __nv_bfloat16 g_wth[(size_t)3*DD*DD], g_wtl[(size_t)3*DD*DD];
__device__ __nv_bfloat16 g_qh[(size_t)MPROJ*DD], g_ql[(size_t)MPROJ*DD];
__device__ __nv_bfloat16 g_kh[(size_t)MPROJ*DD], g_kl[(size_t)MPROJ*DD];
__device__ __nv_bfloat16 g_vh[(size_t)MPROJ*DD], g_vl[(size_t)MPROJ*DD];
__device__ __nv_bfloat16 g_vth[(size_t)MPROJ*DD], g_vtl[(size_t)MPROJ*DD];
__device__ float         g_S [(size_t)BB*SS*SS];
__device__ __nv_bfloat16 g_ph[(size_t)BB*SS*SS], g_pl[(size_t)BB*SS*SS];
__device__ float         g_rsum[(size_t)BB*SS];

// ---------------- PTX helpers (sm_80-level only; NO 'a'-suffix features) ----------------
__device__ __forceinline__ uint32_t smem_u32(const void* p) {
    uint32_t a;
    asm("{ .reg .u64 t; cvta.to.shared.u64 t, %1; cvt.u32.u64 %0, t; }" : "=r"(a) : "l"(p));
    return a;
}
__device__ __forceinline__ void cp_async16(uint32_t dst, const void* src) {
    asm volatile("cp.async.cg.shared.global [%0], [%1], 16;" :: "r"(dst), "l"(src));
}
__device__ __forceinline__ void cp_commit() {
    asm volatile("cp.async.commit_group;" ::: "memory");
}
template <int N>
__device__ __forceinline__ void cp_wait() {
    asm volatile("cp.async.wait_group %0;" :: "n"(N) : "memory");
}
__device__ __forceinline__ void ldsm_x4(uint32_t* r, uint32_t addr) {
    asm volatile("ldmatrix.sync.aligned.m8n8.x4.shared.b16 {%0,%1,%2,%3}, [%4];"
                 : "=r"(r[0]), "=r"(r[1]), "=r"(r[2]), "=r"(r[3]) : "r"(addr));
}
__device__ __forceinline__ void mma16816(float* c, const uint32_t* a, const uint32_t* b) {
    asm volatile(
        "mma.sync.aligned.m16n8k16.row.col.f32.bf16.bf16.f32 "
        "{%0,%1,%2,%3}, {%4,%5,%6,%7}, {%8,%9}, {%0,%1,%2,%3};"
        : "+f"(c[0]), "+f"(c[1]), "+f"(c[2]), "+f"(c[3])
        : "r"(a[0]), "r"(a[1]), "r"(a[2]), "r"(a[3]), "r"(b[0]), "r"(b[1]));
}

// ---------------- GEMM: C[M,N] = A[M,K] @ B[N,K]^T, bf16 hi/lo split, fp32 acc -------
// BM=BN=128, BK=32. 8 warps, warp tile 64x32 (2x4 warp grid).
// smem per stage: 4 matrices (Ah,Al,Bh,Bl) of 128 rows x 80B (32 bf16 + pad) = 40960B.
#define GBM 128
#define GBN 128
#define GBK 32
#define ROWB 80
#define MATB (128*ROWB)          // 10240
#define STAGEB (4*MATB)          // 40960
#define GEMM_SMEM (2*STAGEB)     // 81920

__device__ __forceinline__ void stage_in(
    const __nv_bfloat16* Ah, const __nv_bfloat16* Al,
    const __nv_bfloat16* Bh, const __nv_bfloat16* Bl,
    int ldA, int ldB, int m0, int n0, int k0, uint32_t sb, int tid)
{
#pragma unroll
    for (int i = 0; i < 2; ++i) {
        const int idx = tid + i * 256;
        const int r = idx >> 2, c = idx & 3;          // r: 0..127, c: 16B chunk 0..3
        const uint32_t soff = r * ROWB + c * 16;
        const size_t ga = (size_t)(m0 + r) * ldA + k0 + c * 8;
        const size_t gb = (size_t)(n0 + r) * ldB + k0 + c * 8;
        cp_async16(sb + 0 * MATB + soff, Ah + ga);
        cp_async16(sb + 1 * MATB + soff, Al + ga);
        cp_async16(sb + 2 * MATB + soff, Bh + gb);
        cp_async16(sb + 3 * MATB + soff, Bl + gb);
    }
}

// MODE 0: C fp32 = alpha * D
// MODE 1: split-bf16 outputs routed among 3 target pairs by global n / 1024
// MODE 2: C fp32 = alpha * D / rsum[row]
template <int MODE>
__global__ void __launch_bounds__(256, 2)
tc_gemm(const __nv_bfloat16* __restrict__ Ahi, const __nv_bfloat16* __restrict__ Alo,
        const __nv_bfloat16* __restrict__ Bhi, const __nv_bfloat16* __restrict__ Blo,
        float* __restrict__ Cf,
        __nv_bfloat16* __restrict__ o0h, __nv_bfloat16* __restrict__ o0l,
        __nv_bfloat16* __restrict__ o1h, __nv_bfloat16* __restrict__ o1l,
        __nv_bfloat16* __restrict__ o2h, __nv_bfloat16* __restrict__ o2l,
        int M, int N, int K, int ldA, int ldB,
        size_t zA, size_t zB, size_t zC,
        float alpha, const float* __restrict__ rsum)
{
    extern __shared__ __align__(128) char smem[];
    const uint32_t sbase = smem_u32(smem);
    const int tid = threadIdx.x;
    const int wid = tid >> 5, lane = tid & 31;
    const int wm = wid >> 2, wn = wid & 3;        // warp grid 2 x 4
    const int z = blockIdx.z;
    const int m0 = blockIdx.y * GBM, n0 = blockIdx.x * GBN;

    Ahi += (size_t)z * zA;  Alo += (size_t)z * zA;
    Bhi += (size_t)z * zB;  Blo += (size_t)z * zB;

    float acc[4][4][4];
#pragma unroll
    for (int i = 0; i < 4; ++i)
#pragma unroll
        for (int j = 0; j < 4; ++j)
#pragma unroll
            for (int q = 0; q < 4; ++q) acc[i][j][q] = 0.f;

    const int numT = K / GBK;

    stage_in(Ahi, Alo, Bhi, Blo, ldA, ldB, m0, n0, 0, sbase, tid);
    cp_commit();

    // per-lane ldmatrix address components (byte offsets within a matrix)
    const uint32_t a_row = (uint32_t)(wm * 64 + (lane & 15));
    const uint32_t a_sel = ((lane >> 4) & 1) * 16;              // k-half 16B
    const uint32_t b_row = (uint32_t)(wn * 32 + ((lane >> 4) & 1) * 8 + (lane & 7));
    const uint32_t b_sel = ((lane >> 3) & 1) * 16;

    for (int t = 0; t < numT; ++t) {
        if (t + 1 < numT) {
            stage_in(Ahi, Alo, Bhi, Blo, ldA, ldB, m0, n0, (t + 1) * GBK,
                     sbase + ((t + 1) & 1) * STAGEB, tid);
            cp_commit();
            cp_wait<1>();
        } else {
            cp_wait<0>();
        }
        __syncthreads();

        const uint32_t sbuf = sbase + (t & 1) * STAGEB;
#pragma unroll
        for (int kc = 0; kc < 2; ++kc) {
            const uint32_t kof = kc * 32;   // 16 bf16 = 32B
            uint32_t ah[4][4], al[4][4], bb[4][2];

            const uint32_t abase = sbuf + a_row * ROWB + kof + a_sel;
#pragma unroll
            for (int mt = 0; mt < 4; ++mt) {
                ldsm_x4(ah[mt], abase + mt * (16 * ROWB));
                ldsm_x4(al[mt], abase + MATB + mt * (16 * ROWB));
            }
            const uint32_t bbase = sbuf + 2 * MATB + b_row * ROWB + kof + b_sel;
            ldsm_x4(&bb[0][0], bbase);                 // n-tiles 0,1 (hi)
            ldsm_x4(&bb[2][0], bbase + 16 * ROWB);     // n-tiles 2,3 (hi)
#pragma unroll
            for (int mt = 0; mt < 4; ++mt)
#pragma unroll
                for (int nt = 0; nt < 4; ++nt) mma16816(acc[mt][nt], ah[mt], bb[nt]);
#pragma unroll
            for (int mt = 0; mt < 4; ++mt)
#pragma unroll
                for (int nt = 0; nt < 4; ++nt) mma16816(acc[mt][nt], al[mt], bb[nt]);

            ldsm_x4(&bb[0][0], bbase + MATB);          // lo B
            ldsm_x4(&bb[2][0], bbase + MATB + 16 * ROWB);
#pragma unroll
            for (int mt = 0; mt < 4; ++mt)
#pragma unroll
                for (int nt = 0; nt < 4; ++nt) mma16816(acc[mt][nt], ah[mt], bb[nt]);
        }
        __syncthreads();
    }

    // ---------------- epilogue ----------------
    const int qrow = lane >> 2;          // 0..7
    const int qcol = (lane & 3) * 2;     // 0,2,4,6

#pragma unroll
    for (int mt = 0; mt < 4; ++mt) {
        const int r0 = m0 + wm * 64 + mt * 16 + qrow;     // rows r0, r0+8
        float sc0 = alpha, sc1 = alpha;
        if (MODE == 2) {
            sc0 = alpha / __ldg(&rsum[(size_t)z * M + r0]);
            sc1 = alpha / __ldg(&rsum[(size_t)z * M + r0 + 8]);
        }
#pragma unroll
        for (int nt = 0; nt < 4; ++nt) {
            const int ncol = n0 + wn * 32 + nt * 8 + qcol;
            const float* c = acc[mt][nt];
            if (MODE == 0 || MODE == 2) {
                float* base = Cf + (size_t)z * zC;
                float2 v0 = make_float2(sc0 * c[0], sc0 * c[1]);
                float2 v1 = make_float2(sc1 * c[2], sc1 * c[3]);
                *reinterpret_cast<float2*>(base + (size_t)r0 * N + ncol) = v0;
                *reinterpret_cast<float2*>(base + (size_t)(r0 + 8) * N + ncol) = v1;
            } else {
                const int sel = ncol >> 10;
                __nv_bfloat16* Dh = (sel == 0) ? o0h : ((sel == 1) ? o1h : o2h);
                __nv_bfloat16* Dl = (sel == 0) ? o0l : ((sel == 1) ? o1l : o2l);
                const int cm = ncol & (DD - 1);
#pragma unroll
                for (int h = 0; h < 2; ++h) {
                    const float v0 = c[2 * h], v1 = c[2 * h + 1];
                    __nv_bfloat16 h0 = __float2bfloat16(v0);
                    __nv_bfloat16 h1 = __float2bfloat16(v1);
                    __nv_bfloat16 l0 = __float2bfloat16(v0 - __bfloat162float(h0));
                    __nv_bfloat16 l1 = __float2bfloat16(v1 - __bfloat162float(h1));
                    uint32_t hp = (uint32_t)__bfloat16_as_ushort(h0) |
                                  ((uint32_t)__bfloat16_as_ushort(h1) << 16);
                    uint32_t lp = (uint32_t)__bfloat16_as_ushort(l0) |
                                  ((uint32_t)__bfloat16_as_ushort(l1) << 16);
                    const size_t off = (size_t)(r0 + 8 * h) * DD + cm;
                    *reinterpret_cast<uint32_t*>(Dh + off) = hp;
                    *reinterpret_cast<uint32_t*>(Dl + off) = lp;
                }
            }
        }
    }
}

// ---------------- aux kernels ----------------
__global__ __launch_bounds__(256)
void split_f32(const float* __restrict__ in, __nv_bfloat16* __restrict__ hi,
               __nv_bfloat16* __restrict__ lo, size_t n4)
{
    size_t i = (size_t)blockIdx.x * 256 + threadIdx.x;
    if (i >= n4) return;
    float4 v = reinterpret_cast<const float4*>(in)[i];
    float f[4] = {v.x, v.y, v.z, v.w};
    uint32_t hh[2], ll[2];
#pragma unroll
    for (int j = 0; j < 2; ++j) {
        __nv_bfloat16 h0 = __float2bfloat16(f[2 * j]);
        __nv_bfloat16 h1 = __float2bfloat16(f[2 * j + 1]);
        __nv_bfloat16 l0 = __float2bfloat16(f[2 * j] - __bfloat162float(h0));
        __nv_bfloat16 l1 = __float2bfloat16(f[2 * j + 1] - __bfloat162float(h1));
        hh[j] = (uint32_t)__bfloat16_as_ushort(h0) | ((uint32_t)__bfloat16_as_ushort(h1) << 16);
        ll[j] = (uint32_t)__bfloat16_as_ushort(l0) | ((uint32_t)__bfloat16_as_ushort(l1) << 16);
    }
    reinterpret_cast<uint2*>(hi)[i] = make_uint2(hh[0], hh[1]);
    reinterpret_cast<uint2*>(lo)[i] = make_uint2(ll[0], ll[1]);
}

__global__ __launch_bounds__(256)
void split_w_t(const float* __restrict__ Wq, const float* __restrict__ Wk,
               const float* __restrict__ Wv,
               __nv_bfloat16* __restrict__ th, __nv_bfloat16* __restrict__ tl)
{
    __shared__ float tile[32][33];
    const int zz = blockIdx.z;
    const float* W = (zz == 0) ? Wq : ((zz == 1) ? Wk : Wv);
    const int k0 = blockIdx.x * 32;
    const int n0 = blockIdx.y * 32;
    const int lx = threadIdx.x & 31, ly = threadIdx.x >> 5;
#pragma unroll
    for (int i = 0; i < 32; i += 8)
        tile[ly + i][lx] = W[(size_t)(k0 + ly + i) * DD + n0 + lx];
    __syncthreads();
#pragma unroll
    for (int i = 0; i < 32; i += 8) {
        float v = tile[lx][ly + i];
        __nv_bfloat16 h = __float2bfloat16(v);
        __nv_bfloat16 l = __float2bfloat16(v - __bfloat162float(h));
        size_t o = ((size_t)zz * DD + (n0 + ly + i)) * DD + k0 + lx;
        th[o] = h;
        tl[o] = l;
    }
}

__global__ __launch_bounds__(256)
void transpose_v(const __nv_bfloat16* __restrict__ vh, const __nv_bfloat16* __restrict__ vl,
                 __nv_bfloat16* __restrict__ vth, __nv_bfloat16* __restrict__ vtl)
{
    __shared__ __nv_bfloat16 t0[32][33], t1[32][33];
    const int b = blockIdx.z;
    const int s0 = blockIdx.x * 32, d0 = blockIdx.y * 32;
    const int lx = threadIdx.x & 31, ly = threadIdx.x >> 5;
#pragma unroll
    for (int i = 0; i < 32; i += 8) {
        size_t src = ((size_t)b * SS + s0 + ly + i) * DD + d0 + lx;
        t0[ly + i][lx] = vh[src];
        t1[ly + i][lx] = vl[src];
    }
    __syncthreads();
#pragma unroll
    for (int i = 0; i < 32; i += 8) {
        size_t dst = (size_t)b * SS * DD + (size_t)(d0 + ly + i) * SS + s0 + lx;
        vth[dst] = t0[lx][ly + i];
        vtl[dst] = t1[lx][ly + i];
    }
}

__global__ __launch_bounds__(256)
void softmax_split(const float* __restrict__ S, __nv_bfloat16* __restrict__ Ph,
                   __nv_bfloat16* __restrict__ Pl, float* __restrict__ rsum)
{
    const size_t rbase = (size_t)blockIdx.x * SS;
    const float4* row4 = reinterpret_cast<const float4*>(S + rbase);
    const int tid = threadIdx.x;
    __shared__ float red[8];

    float m = -1e30f;
#pragma unroll 4
    for (int i = tid; i < SS / 4; i += 256) {
        float4 v = row4[i];
        m = fmaxf(m, fmaxf(fmaxf(v.x, v.y), fmaxf(v.z, v.w)));
    }
#pragma unroll
    for (int o = 16; o > 0; o >>= 1) m = fmaxf(m, __shfl_xor_sync(0xffffffffu, m, o));
    if ((tid & 31) == 0) red[tid >> 5] = m;
    __syncthreads();
    if (tid < 32) {
        float v = (tid < 8) ? red[tid] : -1e30f;
#pragma unroll
        for (int o = 4; o > 0; o >>= 1) v = fmaxf(v, __shfl_xor_sync(0xffffffffu, v, o));
        if (tid == 0) red[0] = v;
    }
    __syncthreads();
    const float mx = red[0];
    __syncthreads();

    float s = 0.f;
#pragma unroll 4
    for (int i = tid; i < SS / 4; i += 256) {
        float4 v = row4[i];
        float e0 = __expf(v.x - mx), e1 = __expf(v.y - mx);
        float e2 = __expf(v.z - mx), e3 = __expf(v.w - mx);
        s += (e0 + e1) + (e2 + e3);
        __nv_bfloat16 h0 = __float2bfloat16(e0), h1 = __float2bfloat16(e1);
        __nv_bfloat16 h2 = __float2bfloat16(e2), h3 = __float2bfloat16(e3);
        __nv_bfloat16 l0 = __float2bfloat16(e0 - __bfloat162float(h0));
        __nv_bfloat16 l1 = __float2bfloat16(e1 - __bfloat162float(h1));
        __nv_bfloat16 l2 = __float2bfloat16(e2 - __bfloat162float(h2));
        __nv_bfloat16 l3 = __float2bfloat16(e3 - __bfloat162float(h3));
        uint32_t hA = (uint32_t)__bfloat16_as_ushort(h0) | ((uint32_t)__bfloat16_as_ushort(h1) << 16);
        uint32_t hB = (uint32_t)__bfloat16_as_ushort(h2) | ((uint32_t)__bfloat16_as_ushort(h3) << 16);
        uint32_t lA = (uint32_t)__bfloat16_as_ushort(l0) | ((uint32_t)__bfloat16_as_ushort(l1) << 16);
        uint32_t lB = (uint32_t)__bfloat16_as_ushort(l2) | ((uint32_t)__bfloat16_as_ushort(l3) << 16);
        *reinterpret_cast<uint2*>(Ph + rbase + (size_t)i * 4) = make_uint2(hA, hB);
        *reinterpret_cast<uint2*>(Pl + rbase + (size_t)i * 4) = make_uint2(lA, lB);
    }
#pragma unroll
    for (int o = 16; o > 0; o >>= 1) s += __shfl_xor_sync(0xffffffffu, s, o);
    if ((tid & 31) == 0) red[tid >> 5] = s;
    __syncthreads();
    if (tid == 0) {
        float v = 0.f;
#pragma unroll
        for (int w = 0; w < 8; ++w) v += red[w];
        rsum[blockIdx.x] = v;
    }
}

// ---------------- launch ----------------
extern "C" void kernel_launch(void* const* d_in, const int* in_sizes, int n_in,
                              void* d_out, int out_size)
{
    const float* x  = (const float*)d_in[0];
    const float* Wq = (const float*)d_in[1];
    const float* Wk = (const float*)d_in[2];
    const float* Wv = (const float*)d_in[3];
    float* out = (float*)d_out;

    __nv_bfloat16 *pxh, *pxl, *pwth, *pwtl, *pqh, *pql, *pkh, *pkl, *pvh, *pvl, *pvth, *pvtl, *pph, *ppl;
    float *pS, *prs;
    cudaGetSymbolAddress((void**)&pxh, g_xh);   cudaGetSymbolAddress((void**)&pxl, g_xl);
    cudaGetSymbolAddress((void**)&pwth, g_wth); cudaGetSymbolAddress((void**)&pwtl, g_wtl);
    cudaGetSymbolAddress((void**)&pqh, g_qh);   cudaGetSymbolAddress((void**)&pql, g_ql);
    cudaGetSymbolAddress((void**)&pkh, g_kh);   cudaGetSymbolAddress((void**)&pkl, g_kl);
    cudaGetSymbolAddress((void**)&pvh, g_vh);   cudaGetSymbolAddress((void**)&pvl, g_vl);
    cudaGetSymbolAddress((void**)&pvth, g_vth); cudaGetSymbolAddress((void**)&pvtl, g_vtl);
    cudaGetSymbolAddress((void**)&pph, g_ph);   cudaGetSymbolAddress((void**)&ppl, g_pl);
    cudaGetSymbolAddress((void**)&pS, g_S);     cudaGetSymbolAddress((void**)&prs, g_rsum);

    cudaFuncSetAttribute(tc_gemm<0>, cudaFuncAttributeMaxDynamicSharedMemorySize, GEMM_SMEM);
    cudaFuncSetAttribute(tc_gemm<1>, cudaFuncAttributeMaxDynamicSharedMemorySize, GEMM_SMEM);
    cudaFuncSetAttribute(tc_gemm<2>, cudaFuncAttributeMaxDynamicSharedMemorySize, GEMM_SMEM);

    // 1) split inputs
    split_f32<<<(unsigned)(((size_t)MPROJ * DD / 4 + 255) / 256), 256>>>(x, pxh, pxl, (size_t)MPROJ * DD / 4);
    split_w_t<<<dim3(DD / 32, DD / 32, 3), 256>>>(Wq, Wk, Wv, pwth, pwtl);

    // 2) fused QKV projection: [16384,1024] x [3072,1024]^T, split epilogue
    tc_gemm<1><<<dim3(3 * DD / GBN, MPROJ / GBM, 1), 256, GEMM_SMEM>>>(
        pxh, pxl, pwth, pwtl, nullptr,
        pqh, pql, pkh, pkl, pvh, pvl,
        MPROJ, 3 * DD, DD, DD, DD, 0, 0, 0, 1.0f, nullptr);

    // 3) V transpose (per batch)
    transpose_v<<<dim3(SS / 32, DD / 32, BB), 256>>>(pvh, pvl, pvth, pvtl);

    // 4) scores = (1/32) * Q @ K^T per batch -> fp32
    tc_gemm<0><<<dim3(SS / GBN, SS / GBM, BB), 256, GEMM_SMEM>>>(
        pqh, pql, pkh, pkl, pS,
        nullptr, nullptr, nullptr, nullptr, nullptr, nullptr,
        SS, SS, DD, DD, DD,
        (size_t)SS * DD, (size_t)SS * DD, (size_t)SS * SS, 1.0f / 32.0f, nullptr);

    // 5) softmax -> split exp + row sums
    softmax_split<<<BB * SS, 256>>>(pS, pph, ppl, prs);

    // 6) out = (P @ Vt^T) / rsum per batch
    tc_gemm<2><<<dim3(DD / GBN, SS / GBM, BB), 256, GEMM_SMEM>>>(
        pph, ppl, pvth, pvtl, out,
        nullptr, nullptr, nullptr, nullptr, nullptr, nullptr,
        SS, DD, SS, SS, SS,
        (size_t)SS * SS, (size_t)SS * DD, (size_t)SS * DD, 1.0f, prs);
}

// round 4
// speedup vs baseline: 2.9628x; 1.0959x over previous
#include <cuda_runtime.h>
#include <cuda_bf16.h>
#include <stdint.h>
#include <math.h>

#define BB 4
#define SS 4096
#define DD 1024
#define MPROJ (BB*SS)

// ---------------- device scratch ----------------
__device__ __nv_bfloat16 g_xh[(size_t)MPROJ*DD], g_xl[(size_t)MPROJ*DD];
__device__ __nv_bfloat16 g_wth[(size_t)3*DD*DD], g_wtl[(size_t)3*DD*DD];
__device__ __nv_bfloat16 g_qh[(size_t)MPROJ*DD], g_ql[(size_t)MPROJ*DD];
__device__ __nv_bfloat16 g_kh[(size_t)MPROJ*DD], g_kl[(size_t)MPROJ*DD];
__device__ __nv_bfloat16 g_vh[(size_t)MPROJ*DD], g_vl[(size_t)MPROJ*DD];
__device__ __nv_bfloat16 g_vth[(size_t)MPROJ*DD], g_vtl[(size_t)MPROJ*DD];
__device__ float         g_S [(size_t)BB*SS*SS];
__device__ __nv_bfloat16 g_ph[(size_t)BB*SS*SS], g_pl[(size_t)BB*SS*SS];
__device__ float         g_rsum[(size_t)BB*SS];

// ---------------- PTX helpers (sm_80-level; no 'a'-suffix features) ----------------
__device__ __forceinline__ uint32_t smem_u32(const void* p) {
    uint32_t a;
    asm("{ .reg .u64 t; cvta.to.shared.u64 t, %1; cvt.u32.u64 %0, t; }" : "=r"(a) : "l"(p));
    return a;
}
__device__ __forceinline__ void cp_async16(uint32_t dst, const void* src) {
    asm volatile("cp.async.cg.shared.global [%0], [%1], 16;" :: "r"(dst), "l"(src));
}
__device__ __forceinline__ void cp_commit() {
    asm volatile("cp.async.commit_group;" ::: "memory");
}
template <int N>
__device__ __forceinline__ void cp_wait() {
    asm volatile("cp.async.wait_group %0;" :: "n"(N) : "memory");
}
__device__ __forceinline__ void ldsm_x4(uint32_t* r, uint32_t addr) {
    asm volatile("ldmatrix.sync.aligned.m8n8.x4.shared.b16 {%0,%1,%2,%3}, [%4];"
                 : "=r"(r[0]), "=r"(r[1]), "=r"(r[2]), "=r"(r[3]) : "r"(addr));
}
__device__ __forceinline__ void mma16816(float* c, const uint32_t* a, const uint32_t* b) {
    asm volatile(
        "mma.sync.aligned.m16n8k16.row.col.f32.bf16.bf16.f32 "
        "{%0,%1,%2,%3}, {%4,%5,%6,%7}, {%8,%9}, {%0,%1,%2,%3};"
        : "+f"(c[0]), "+f"(c[1]), "+f"(c[2]), "+f"(c[3])
        : "r"(a[0]), "r"(a[1]), "r"(a[2]), "r"(a[3]), "r"(b[0]), "r"(b[1]));
}

// ---------------- GEMM: C[M,N] = A[M,K] @ B[N,K]^T, bf16 hi/lo split, fp32 acc -------
// BM=BN=128, BK=64, swizzled 128B rows (no pad), 3-stage cp.async pipeline.
// 8 warps, warp tile 64x32 (warp grid 2x4).
#define GBM 128
#define GBN 128
#define GBK 64
#define MATB (128*128)            // 16384 B per matrix per stage
#define STAGEB (4*MATB)           // 65536
#define NSTAGE 3
#define GEMM_SMEM (NSTAGE*STAGEB) // 196608

// swizzled in-stage offset for (row, c16): row*128 + ((c16 ^ (row&7))<<4)
__device__ __forceinline__ void stage_in(
    const __nv_bfloat16* Ah, const __nv_bfloat16* Al,
    const __nv_bfloat16* Bh, const __nv_bfloat16* Bl,
    int ldA, int ldB, int m0, int n0, int k0, uint32_t sb, int tid)
{
#pragma unroll
    for (int i = 0; i < 4; ++i) {
        const int idx = tid + i * 256;        // 0..1023
        const int r = idx >> 3, c16 = idx & 7;
        const uint32_t soff = (uint32_t)(r * 128 + (((c16 ^ (r & 7)) << 4)));
        const size_t ga = (size_t)(m0 + r) * ldA + k0 + c16 * 8;
        const size_t gb = (size_t)(n0 + r) * ldB + k0 + c16 * 8;
        cp_async16(sb + 0 * MATB + soff, Ah + ga);
        cp_async16(sb + 1 * MATB + soff, Al + ga);
        cp_async16(sb + 2 * MATB + soff, Bh + gb);
        cp_async16(sb + 3 * MATB + soff, Bl + gb);
    }
}

// MODE 0: C fp32 = alpha * D
// MODE 1: split-bf16 outputs routed among 3 target pairs by global n / 1024
// MODE 2: C fp32 = alpha * D / rsum[row]
template <int MODE>
__global__ void __launch_bounds__(256, 1)
tc_gemm(const __nv_bfloat16* __restrict__ Ahi, const __nv_bfloat16* __restrict__ Alo,
        const __nv_bfloat16* __restrict__ Bhi, const __nv_bfloat16* __restrict__ Blo,
        float* __restrict__ Cf,
        __nv_bfloat16* __restrict__ o0h, __nv_bfloat16* __restrict__ o0l,
        __nv_bfloat16* __restrict__ o1h, __nv_bfloat16* __restrict__ o1l,
        __nv_bfloat16* __restrict__ o2h, __nv_bfloat16* __restrict__ o2l,
        int M, int N, int K, int ldA, int ldB,
        size_t zA, size_t zB, size_t zC,
        float alpha, const float* __restrict__ rsum)
{
    extern __shared__ __align__(128) char smem[];
    const uint32_t sbase = smem_u32(smem);
    const int tid = threadIdx.x;
    const int wid = tid >> 5, lane = tid & 31;
    const int wm = wid >> 2, wn = wid & 3;        // warp grid 2 x 4
    const int z = blockIdx.z;
    const int m0 = blockIdx.y * GBM, n0 = blockIdx.x * GBN;

    Ahi += (size_t)z * zA;  Alo += (size_t)z * zA;
    Bhi += (size_t)z * zB;  Blo += (size_t)z * zB;

    float acc[4][4][4];
#pragma unroll
    for (int i = 0; i < 4; ++i)
#pragma unroll
        for (int j = 0; j < 4; ++j)
#pragma unroll
            for (int q = 0; q < 4; ++q) acc[i][j][q] = 0.f;

    const int numT = K / GBK;

    // prologue: stages 0,1
    stage_in(Ahi, Alo, Bhi, Blo, ldA, ldB, m0, n0, 0, sbase, tid);
    cp_commit();
    stage_in(Ahi, Alo, Bhi, Blo, ldA, ldB, m0, n0, GBK, sbase + STAGEB, tid);
    cp_commit();

    // per-lane ldmatrix components
    const int a_row = wm * 64 + (lane & 15);
    const uint32_t a_rl = (uint32_t)(a_row & 7);
    const uint32_t a_hi4 = (uint32_t)(lane >> 4);          // 0/1 -> +1 c16
    const uint32_t a_off = (uint32_t)(a_row * 128);

    const int b_row = wn * 32 + ((lane >> 4) & 1) * 8 + (lane & 7);
    const uint32_t b_rl = (uint32_t)(b_row & 7);
    const uint32_t b_hi = (uint32_t)((lane >> 3) & 1);
    const uint32_t b_off = (uint32_t)(b_row * 128);

    int sidx = 0;  // stage index of tile t
    for (int t = 0; t < numT; ++t) {
        cp_wait<1>();
        __syncthreads();

        // issue loads for stage t+2 (overwrites buffer released by the sync)
        if (t + 2 < numT) {
            int ws = sidx + 2; if (ws >= NSTAGE) ws -= NSTAGE;
            stage_in(Ahi, Alo, Bhi, Blo, ldA, ldB, m0, n0, (t + 2) * GBK,
                     sbase + ws * STAGEB, tid);
        }

        const uint32_t sbuf = sbase + sidx * STAGEB;
#pragma unroll
        for (int kc = 0; kc < 4; ++kc) {
            uint32_t ah[4][4], al[4][4], bb[4][2];

            const uint32_t a_x = ((((uint32_t)(kc * 2) + a_hi4) ^ a_rl) << 4);
            const uint32_t abase = sbuf + a_off + a_x;
#pragma unroll
            for (int mt = 0; mt < 4; ++mt) {
                ldsm_x4(ah[mt], abase + mt * (16 * 128));
                ldsm_x4(al[mt], abase + MATB + mt * (16 * 128));
            }
            const uint32_t b_x = ((((uint32_t)(kc * 2) + b_hi) ^ b_rl) << 4);
            const uint32_t bbase = sbuf + 2 * MATB + b_off + b_x;
            ldsm_x4(&bb[0][0], bbase);                 // n-tiles 0,1 (hi)
            ldsm_x4(&bb[2][0], bbase + 16 * 128);      // n-tiles 2,3 (hi)
#pragma unroll
            for (int mt = 0; mt < 4; ++mt)
#pragma unroll
                for (int nt = 0; nt < 4; ++nt) mma16816(acc[mt][nt], ah[mt], bb[nt]);
#pragma unroll
            for (int mt = 0; mt < 4; ++mt)
#pragma unroll
                for (int nt = 0; nt < 4; ++nt) mma16816(acc[mt][nt], al[mt], bb[nt]);

            ldsm_x4(&bb[0][0], bbase + MATB);          // lo B
            ldsm_x4(&bb[2][0], bbase + MATB + 16 * 128);
#pragma unroll
            for (int mt = 0; mt < 4; ++mt)
#pragma unroll
                for (int nt = 0; nt < 4; ++nt) mma16816(acc[mt][nt], ah[mt], bb[nt]);
        }

        cp_commit();
        if (++sidx == NSTAGE) sidx = 0;
    }

    // ---------------- epilogue ----------------
    const int qrow = lane >> 2;          // 0..7
    const int qcol = (lane & 3) * 2;     // 0,2,4,6

#pragma unroll
    for (int mt = 0; mt < 4; ++mt) {
        const int r0 = m0 + wm * 64 + mt * 16 + qrow;     // rows r0, r0+8
        float sc0 = alpha, sc1 = alpha;
        if (MODE == 2) {
            sc0 = alpha / __ldg(&rsum[(size_t)z * M + r0]);
            sc1 = alpha / __ldg(&rsum[(size_t)z * M + r0 + 8]);
        }
#pragma unroll
        for (int nt = 0; nt < 4; ++nt) {
            const int ncol = n0 + wn * 32 + nt * 8 + qcol;
            const float* c = acc[mt][nt];
            if (MODE == 0 || MODE == 2) {
                float* base = Cf + (size_t)z * zC;
                float2 v0 = make_float2(sc0 * c[0], sc0 * c[1]);
                float2 v1 = make_float2(sc1 * c[2], sc1 * c[3]);
                *reinterpret_cast<float2*>(base + (size_t)r0 * N + ncol) = v0;
                *reinterpret_cast<float2*>(base + (size_t)(r0 + 8) * N + ncol) = v1;
            } else {
                const int sel = ncol >> 10;
                __nv_bfloat16* Dh = (sel == 0) ? o0h : ((sel == 1) ? o1h : o2h);
                __nv_bfloat16* Dl = (sel == 0) ? o0l : ((sel == 1) ? o1l : o2l);
                const int cm = ncol & (DD - 1);
#pragma unroll
                for (int h = 0; h < 2; ++h) {
                    const float v0 = c[2 * h], v1 = c[2 * h + 1];
                    __nv_bfloat16 h0 = __float2bfloat16(v0);
                    __nv_bfloat16 h1 = __float2bfloat16(v1);
                    __nv_bfloat16 l0 = __float2bfloat16(v0 - __bfloat162float(h0));
                    __nv_bfloat16 l1 = __float2bfloat16(v1 - __bfloat162float(h1));
                    uint32_t hp = (uint32_t)__bfloat16_as_ushort(h0) |
                                  ((uint32_t)__bfloat16_as_ushort(h1) << 16);
                    uint32_t lp = (uint32_t)__bfloat16_as_ushort(l0) |
                                  ((uint32_t)__bfloat16_as_ushort(l1) << 16);
                    const size_t off = (size_t)(r0 + 8 * h) * DD + cm;
                    *reinterpret_cast<uint32_t*>(Dh + off) = hp;
                    *reinterpret_cast<uint32_t*>(Dl + off) = lp;
                }
            }
        }
    }
}

// ---------------- aux kernels ----------------
__global__ __launch_bounds__(256)
void split_f32(const float* __restrict__ in, __nv_bfloat16* __restrict__ hi,
               __nv_bfloat16* __restrict__ lo, size_t n4)
{
    size_t i = (size_t)blockIdx.x * 256 + threadIdx.x;
    if (i >= n4) return;
    float4 v = reinterpret_cast<const float4*>(in)[i];
    float f[4] = {v.x, v.y, v.z, v.w};
    uint32_t hh[2], ll[2];
#pragma unroll
    for (int j = 0; j < 2; ++j) {
        __nv_bfloat16 h0 = __float2bfloat16(f[2 * j]);
        __nv_bfloat16 h1 = __float2bfloat16(f[2 * j + 1]);
        __nv_bfloat16 l0 = __float2bfloat16(f[2 * j] - __bfloat162float(h0));
        __nv_bfloat16 l1 = __float2bfloat16(f[2 * j + 1] - __bfloat162float(h1));
        hh[j] = (uint32_t)__bfloat16_as_ushort(h0) | ((uint32_t)__bfloat16_as_ushort(h1) << 16);
        ll[j] = (uint32_t)__bfloat16_as_ushort(l0) | ((uint32_t)__bfloat16_as_ushort(l1) << 16);
    }
    reinterpret_cast<uint2*>(hi)[i] = make_uint2(hh[0], hh[1]);
    reinterpret_cast<uint2*>(lo)[i] = make_uint2(ll[0], ll[1]);
}

__global__ __launch_bounds__(256)
void split_w_t(const float* __restrict__ Wq, const float* __restrict__ Wk,
               const float* __restrict__ Wv,
               __nv_bfloat16* __restrict__ th, __nv_bfloat16* __restrict__ tl)
{
    __shared__ float tile[32][33];
    const int zz = blockIdx.z;
    const float* W = (zz == 0) ? Wq : ((zz == 1) ? Wk : Wv);
    const int k0 = blockIdx.x * 32;
    const int n0 = blockIdx.y * 32;
    const int lx = threadIdx.x & 31, ly = threadIdx.x >> 5;
#pragma unroll
    for (int i = 0; i < 32; i += 8)
        tile[ly + i][lx] = W[(size_t)(k0 + ly + i) * DD + n0 + lx];
    __syncthreads();
#pragma unroll
    for (int i = 0; i < 32; i += 8) {
        float v = tile[lx][ly + i];
        __nv_bfloat16 h = __float2bfloat16(v);
        __nv_bfloat16 l = __float2bfloat16(v - __bfloat162float(h));
        size_t o = ((size_t)zz * DD + (n0 + ly + i)) * DD + k0 + lx;
        th[o] = h;
        tl[o] = l;
    }
}

__global__ __launch_bounds__(256)
void transpose_v(const __nv_bfloat16* __restrict__ vh, const __nv_bfloat16* __restrict__ vl,
                 __nv_bfloat16* __restrict__ vth, __nv_bfloat16* __restrict__ vtl)
{
    __shared__ __nv_bfloat16 t0[32][33], t1[32][33];
    const int b = blockIdx.z;
    const int s0 = blockIdx.x * 32, d0 = blockIdx.y * 32;
    const int lx = threadIdx.x & 31, ly = threadIdx.x >> 5;
#pragma unroll
    for (int i = 0; i < 32; i += 8) {
        size_t src = ((size_t)b * SS + s0 + ly + i) * DD + d0 + lx;
        t0[ly + i][lx] = vh[src];
        t1[ly + i][lx] = vl[src];
    }
    __syncthreads();
#pragma unroll
    for (int i = 0; i < 32; i += 8) {
        size_t dst = (size_t)b * SS * DD + (size_t)(d0 + ly + i) * SS + s0 + lx;
        vth[dst] = t0[lx][ly + i];
        vtl[dst] = t1[lx][ly + i];
    }
}

__global__ __launch_bounds__(256)
void softmax_split(const float* __restrict__ S, __nv_bfloat16* __restrict__ Ph,
                   __nv_bfloat16* __restrict__ Pl, float* __restrict__ rsum)
{
    const size_t rbase = (size_t)blockIdx.x * SS;
    const float4* row4 = reinterpret_cast<const float4*>(S + rbase);
    const int tid = threadIdx.x;
    __shared__ float red[8];

    float m = -1e30f;
#pragma unroll 4
    for (int i = tid; i < SS / 4; i += 256) {
        float4 v = row4[i];
        m = fmaxf(m, fmaxf(fmaxf(v.x, v.y), fmaxf(v.z, v.w)));
    }
#pragma unroll
    for (int o = 16; o > 0; o >>= 1) m = fmaxf(m, __shfl_xor_sync(0xffffffffu, m, o));
    if ((tid & 31) == 0) red[tid >> 5] = m;
    __syncthreads();
    if (tid < 32) {
        float v = (tid < 8) ? red[tid] : -1e30f;
#pragma unroll
        for (int o = 4; o > 0; o >>= 1) v = fmaxf(v, __shfl_xor_sync(0xffffffffu, v, o));
        if (tid == 0) red[0] = v;
    }
    __syncthreads();
    const float mx = red[0];
    __syncthreads();

    float s = 0.f;
#pragma unroll 4
    for (int i = tid; i < SS / 4; i += 256) {
        float4 v = row4[i];
        float e0 = __expf(v.x - mx), e1 = __expf(v.y - mx);
        float e2 = __expf(v.z - mx), e3 = __expf(v.w - mx);
        s += (e0 + e1) + (e2 + e3);
        __nv_bfloat16 h0 = __float2bfloat16(e0), h1 = __float2bfloat16(e1);
        __nv_bfloat16 h2 = __float2bfloat16(e2), h3 = __float2bfloat16(e3);
        __nv_bfloat16 l0 = __float2bfloat16(e0 - __bfloat162float(h0));
        __nv_bfloat16 l1 = __float2bfloat16(e1 - __bfloat162float(h1));
        __nv_bfloat16 l2 = __float2bfloat16(e2 - __bfloat162float(h2));
        __nv_bfloat16 l3 = __float2bfloat16(e3 - __bfloat162float(h3));
        uint32_t hA = (uint32_t)__bfloat16_as_ushort(h0) | ((uint32_t)__bfloat16_as_ushort(h1) << 16);
        uint32_t hB = (uint32_t)__bfloat16_as_ushort(h2) | ((uint32_t)__bfloat16_as_ushort(h3) << 16);
        uint32_t lA = (uint32_t)__bfloat16_as_ushort(l0) | ((uint32_t)__bfloat16_as_ushort(l1) << 16);
        uint32_t lB = (uint32_t)__bfloat16_as_ushort(l2) | ((uint32_t)__bfloat16_as_ushort(l3) << 16);
        *reinterpret_cast<uint2*>(Ph + rbase + (size_t)i * 4) = make_uint2(hA, hB);
        *reinterpret_cast<uint2*>(Pl + rbase + (size_t)i * 4) = make_uint2(lA, lB);
    }
#pragma unroll
    for (int o = 16; o > 0; o >>= 1) s += __shfl_xor_sync(0xffffffffu, s, o);
    if ((tid & 31) == 0) red[tid >> 5] = s;
    __syncthreads();
    if (tid == 0) {
        float v = 0.f;
#pragma unroll
        for (int w = 0; w < 8; ++w) v += red[w];
        rsum[blockIdx.x] = v;
    }
}

// ---------------- launch ----------------
extern "C" void kernel_launch(void* const* d_in, const int* in_sizes, int n_in,
                              void* d_out, int out_size)
{
    const float* x  = (const float*)d_in[0];
    const float* Wq = (const float*)d_in[1];
    const float* Wk = (const float*)d_in[2];
    const float* Wv = (const float*)d_in[3];
    float* out = (float*)d_out;

    __nv_bfloat16 *pxh, *pxl, *pwth, *pwtl, *pqh, *pql, *pkh, *pkl, *pvh, *pvl, *pvth, *pvtl, *pph, *ppl;
    float *pS, *prs;
    cudaGetSymbolAddress((void**)&pxh, g_xh);   cudaGetSymbolAddress((void**)&pxl, g_xl);
    cudaGetSymbolAddress((void**)&pwth, g_wth); cudaGetSymbolAddress((void**)&pwtl, g_wtl);
    cudaGetSymbolAddress((void**)&pqh, g_qh);   cudaGetSymbolAddress((void**)&pql, g_ql);
    cudaGetSymbolAddress((void**)&pkh, g_kh);   cudaGetSymbolAddress((void**)&pkl, g_kl);
    cudaGetSymbolAddress((void**)&pvh, g_vh);   cudaGetSymbolAddress((void**)&pvl, g_vl);
    cudaGetSymbolAddress((void**)&pvth, g_vth); cudaGetSymbolAddress((void**)&pvtl, g_vtl);
    cudaGetSymbolAddress((void**)&pph, g_ph);   cudaGetSymbolAddress((void**)&ppl, g_pl);
    cudaGetSymbolAddress((void**)&pS, g_S);     cudaGetSymbolAddress((void**)&prs, g_rsum);

    cudaFuncSetAttribute(tc_gemm<0>, cudaFuncAttributeMaxDynamicSharedMemorySize, GEMM_SMEM);
    cudaFuncSetAttribute(tc_gemm<1>, cudaFuncAttributeMaxDynamicSharedMemorySize, GEMM_SMEM);
    cudaFuncSetAttribute(tc_gemm<2>, cudaFuncAttributeMaxDynamicSharedMemorySize, GEMM_SMEM);

    // 1) split inputs
    split_f32<<<(unsigned)(((size_t)MPROJ * DD / 4 + 255) / 256), 256>>>(x, pxh, pxl, (size_t)MPROJ * DD / 4);
    split_w_t<<<dim3(DD / 32, DD / 32, 3), 256>>>(Wq, Wk, Wv, pwth, pwtl);

    // 2) fused QKV projection: [16384,1024] x [3072,1024]^T, split epilogue
    tc_gemm<1><<<dim3(3 * DD / GBN, MPROJ / GBM, 1), 256, GEMM_SMEM>>>(
        pxh, pxl, pwth, pwtl, nullptr,
        pqh, pql, pkh, pkl, pvh, pvl,
        MPROJ, 3 * DD, DD, DD, DD, 0, 0, 0, 1.0f, nullptr);

    // 3) V transpose (per batch)
    transpose_v<<<dim3(SS / 32, DD / 32, BB), 256>>>(pvh, pvl, pvth, pvtl);

    // 4) scores = (1/32) * Q @ K^T per batch -> fp32
    tc_gemm<0><<<dim3(SS / GBN, SS / GBM, BB), 256, GEMM_SMEM>>>(
        pqh, pql, pkh, pkl, pS,
        nullptr, nullptr, nullptr, nullptr, nullptr, nullptr,
        SS, SS, DD, DD, DD,
        (size_t)SS * DD, (size_t)SS * DD, (size_t)SS * SS, 1.0f / 32.0f, nullptr);

    // 5) softmax -> split exp + row sums
    softmax_split<<<BB * SS, 256>>>(pS, pph, ppl, prs);

    // 6) out = (P @ Vt^T) / rsum per batch
    tc_gemm<2><<<dim3(DD / GBN, SS / GBM, BB), 256, GEMM_SMEM>>>(
        pph, ppl, pvth, pvtl, out,
        nullptr, nullptr, nullptr, nullptr, nullptr, nullptr,
        SS, DD, SS, SS, SS,
        (size_t)SS * SS, (size_t)SS * DD, (size_t)SS * DD, 1.0f, prs);
}

// round 5
// speedup vs baseline: 2.9673x; 1.0015x over previous
#include <cuda_runtime.h>
#include <cuda_bf16.h>
#include <stdint.h>
#include <math.h>

#define BB 4
#define SS 4096
#define DD 1024
#define MPROJ (BB*SS)

// ---------------- device scratch ----------------
__device__ __nv_bfloat16 g_xh[(size_t)MPROJ*DD], g_xl[(size_t)MPROJ*DD];
__device__ __nv_bfloat16 g_wth[(size_t)3*DD*DD], g_wtl[(size_t)3*DD*DD];
__device__ __nv_bfloat16 g_qh[(size_t)MPROJ*DD], g_ql[(size_t)MPROJ*DD];
__device__ __nv_bfloat16 g_kh[(size_t)MPROJ*DD], g_kl[(size_t)MPROJ*DD];
__device__ __nv_bfloat16 g_vh[(size_t)MPROJ*DD], g_vl[(size_t)MPROJ*DD];
__device__ __nv_bfloat16 g_vth[(size_t)MPROJ*DD], g_vtl[(size_t)MPROJ*DD];
__device__ __nv_bfloat16 g_ph[(size_t)BB*SS*SS], g_pl[(size_t)BB*SS*SS];
__device__ float         g_part[(size_t)BB*SS*32];   // per-(row, colTile) exp partial sums
__device__ float         g_rsum[(size_t)BB*SS];

// ---------------- PTX helpers (sm_80-level; no 'a'-suffix features) ----------------
__device__ __forceinline__ uint32_t smem_u32(const void* p) {
    uint32_t a;
    asm("{ .reg .u64 t; cvta.to.shared.u64 t, %1; cvt.u32.u64 %0, t; }" : "=r"(a) : "l"(p));
    return a;
}
__device__ __forceinline__ void cp_async16(uint32_t dst, const void* src) {
    asm volatile("cp.async.cg.shared.global [%0], [%1], 16;" :: "r"(dst), "l"(src));
}
__device__ __forceinline__ void cp_commit() {
    asm volatile("cp.async.commit_group;" ::: "memory");
}
template <int N>
__device__ __forceinline__ void cp_wait() {
    asm volatile("cp.async.wait_group %0;" :: "n"(N) : "memory");
}
__device__ __forceinline__ void ldsm_x4(uint32_t* r, uint32_t addr) {
    asm volatile("ldmatrix.sync.aligned.m8n8.x4.shared.b16 {%0,%1,%2,%3}, [%4];"
                 : "=r"(r[0]), "=r"(r[1]), "=r"(r[2]), "=r"(r[3]) : "r"(addr));
}
__device__ __forceinline__ void mma16816(float* c, const uint32_t* a, const uint32_t* b) {
    asm volatile(
        "mma.sync.aligned.m16n8k16.row.col.f32.bf16.bf16.f32 "
        "{%0,%1,%2,%3}, {%4,%5,%6,%7}, {%8,%9}, {%0,%1,%2,%3};"
        : "+f"(c[0]), "+f"(c[1]), "+f"(c[2]), "+f"(c[3])
        : "r"(a[0]), "r"(a[1]), "r"(a[2]), "r"(a[3]), "r"(b[0]), "r"(b[1]));
}
__device__ __forceinline__ void pack_split(float v0, float v1, uint32_t& hp, uint32_t& lp) {
    __nv_bfloat16 h0 = __float2bfloat16(v0);
    __nv_bfloat16 h1 = __float2bfloat16(v1);
    __nv_bfloat16 l0 = __float2bfloat16(v0 - __bfloat162float(h0));
    __nv_bfloat16 l1 = __float2bfloat16(v1 - __bfloat162float(h1));
    hp = (uint32_t)__bfloat16_as_ushort(h0) | ((uint32_t)__bfloat16_as_ushort(h1) << 16);
    lp = (uint32_t)__bfloat16_as_ushort(l0) | ((uint32_t)__bfloat16_as_ushort(l1) << 16);
}

// ---------------- GEMM: C[M,N] = A[M,K] @ B[N,K]^T, bf16 hi/lo split, fp32 acc -------
#define GBM 128
#define GBN 128
#define GBK 64
#define MATB (128*128)
#define STAGEB (4*MATB)
#define NSTAGE 3
#define GEMM_SMEM (NSTAGE*STAGEB)

__device__ __forceinline__ void stage_in(
    const __nv_bfloat16* Ah, const __nv_bfloat16* Al,
    const __nv_bfloat16* Bh, const __nv_bfloat16* Bl,
    int ldA, int ldB, int m0, int n0, int k0, uint32_t sb, int tid)
{
#pragma unroll
    for (int i = 0; i < 4; ++i) {
        const int idx = tid + i * 256;
        const int r = idx >> 3, c16 = idx & 7;
        const uint32_t soff = (uint32_t)(r * 128 + (((c16 ^ (r & 7)) << 4)));
        const size_t ga = (size_t)(m0 + r) * ldA + k0 + c16 * 8;
        const size_t gb = (size_t)(n0 + r) * ldB + k0 + c16 * 8;
        cp_async16(sb + 0 * MATB + soff, Ah + ga);
        cp_async16(sb + 1 * MATB + soff, Al + ga);
        cp_async16(sb + 2 * MATB + soff, Bh + gb);
        cp_async16(sb + 3 * MATB + soff, Bl + gb);
    }
}

// MODE 1: split-bf16 outputs routed among 3 target pairs by global n / 1024 (projection)
// MODE 2: C fp32 = alpha * D / rsum[row]                                   (PV)
// MODE 3: P = exp(alpha*D) split-bf16 to o0h/o0l + per-(row,ctaX) partial sums (QK+softmax)
template <int MODE>
__global__ void __launch_bounds__(256, 1)
tc_gemm(const __nv_bfloat16* __restrict__ Ahi, const __nv_bfloat16* __restrict__ Alo,
        const __nv_bfloat16* __restrict__ Bhi, const __nv_bfloat16* __restrict__ Blo,
        float* __restrict__ Cf,
        __nv_bfloat16* __restrict__ o0h, __nv_bfloat16* __restrict__ o0l,
        __nv_bfloat16* __restrict__ o1h, __nv_bfloat16* __restrict__ o1l,
        __nv_bfloat16* __restrict__ o2h, __nv_bfloat16* __restrict__ o2l,
        int M, int N, int K, int ldA, int ldB,
        size_t zA, size_t zB, size_t zC,
        float alpha, const float* __restrict__ rsum, float* __restrict__ part)
{
    extern __shared__ __align__(128) char smem[];
    const uint32_t sbase = smem_u32(smem);
    const int tid = threadIdx.x;
    const int wid = tid >> 5, lane = tid & 31;
    const int wm = wid >> 2, wn = wid & 3;
    const int z = blockIdx.z;
    const int m0 = blockIdx.y * GBM, n0 = blockIdx.x * GBN;

    Ahi += (size_t)z * zA;  Alo += (size_t)z * zA;
    Bhi += (size_t)z * zB;  Blo += (size_t)z * zB;

    float acc[4][4][4];
#pragma unroll
    for (int i = 0; i < 4; ++i)
#pragma unroll
        for (int j = 0; j < 4; ++j)
#pragma unroll
            for (int q = 0; q < 4; ++q) acc[i][j][q] = 0.f;

    const int numT = K / GBK;

    stage_in(Ahi, Alo, Bhi, Blo, ldA, ldB, m0, n0, 0, sbase, tid);
    cp_commit();
    stage_in(Ahi, Alo, Bhi, Blo, ldA, ldB, m0, n0, GBK, sbase + STAGEB, tid);
    cp_commit();

    const int a_row = wm * 64 + (lane & 15);
    const uint32_t a_rl = (uint32_t)(a_row & 7);
    const uint32_t a_hi4 = (uint32_t)(lane >> 4);
    const uint32_t a_off = (uint32_t)(a_row * 128);

    const int b_row = wn * 32 + ((lane >> 4) & 1) * 8 + (lane & 7);
    const uint32_t b_rl = (uint32_t)(b_row & 7);
    const uint32_t b_hi = (uint32_t)((lane >> 3) & 1);
    const uint32_t b_off = (uint32_t)(b_row * 128);

    int sidx = 0;
    for (int t = 0; t < numT; ++t) {
        cp_wait<1>();
        __syncthreads();

        if (t + 2 < numT) {
            int ws = sidx + 2; if (ws >= NSTAGE) ws -= NSTAGE;
            stage_in(Ahi, Alo, Bhi, Blo, ldA, ldB, m0, n0, (t + 2) * GBK,
                     sbase + ws * STAGEB, tid);
        }

        const uint32_t sbuf = sbase + sidx * STAGEB;
#pragma unroll
        for (int kc = 0; kc < 4; ++kc) {
            uint32_t ah[4][4], al[4][4], bb[4][2];

            const uint32_t a_x = ((((uint32_t)(kc * 2) + a_hi4) ^ a_rl) << 4);
            const uint32_t abase = sbuf + a_off + a_x;
#pragma unroll
            for (int mt = 0; mt < 4; ++mt) {
                ldsm_x4(ah[mt], abase + mt * (16 * 128));
                ldsm_x4(al[mt], abase + MATB + mt * (16 * 128));
            }
            const uint32_t b_x = ((((uint32_t)(kc * 2) + b_hi) ^ b_rl) << 4);
            const uint32_t bbase = sbuf + 2 * MATB + b_off + b_x;
            ldsm_x4(&bb[0][0], bbase);
            ldsm_x4(&bb[2][0], bbase + 16 * 128);
#pragma unroll
            for (int mt = 0; mt < 4; ++mt)
#pragma unroll
                for (int nt = 0; nt < 4; ++nt) mma16816(acc[mt][nt], ah[mt], bb[nt]);
#pragma unroll
            for (int mt = 0; mt < 4; ++mt)
#pragma unroll
                for (int nt = 0; nt < 4; ++nt) mma16816(acc[mt][nt], al[mt], bb[nt]);

            ldsm_x4(&bb[0][0], bbase + MATB);
            ldsm_x4(&bb[2][0], bbase + MATB + 16 * 128);
#pragma unroll
            for (int mt = 0; mt < 4; ++mt)
#pragma unroll
                for (int nt = 0; nt < 4; ++nt) mma16816(acc[mt][nt], ah[mt], bb[nt]);
        }

        cp_commit();
        if (++sidx == NSTAGE) sidx = 0;
    }

    // ---------------- epilogue ----------------
    const int qrow = lane >> 2;
    const int qcol = (lane & 3) * 2;

    if (MODE == 3) {
        // fused exp + split-store + row partial sums
        __syncthreads();                        // smem re-used for row sums
        float* psum = reinterpret_cast<float*>(smem);
        float rsloc[4][2];
#pragma unroll
        for (int mt = 0; mt < 4; ++mt) { rsloc[mt][0] = 0.f; rsloc[mt][1] = 0.f; }

#pragma unroll
        for (int mt = 0; mt < 4; ++mt) {
            const int r0 = m0 + wm * 64 + mt * 16 + qrow;
#pragma unroll
            for (int nt = 0; nt < 4; ++nt) {
                const int ncol = n0 + wn * 32 + nt * 8 + qcol;
                const float* c = acc[mt][nt];
                const float e0 = __expf(alpha * c[0]);
                const float e1 = __expf(alpha * c[1]);
                const float e2 = __expf(alpha * c[2]);
                const float e3 = __expf(alpha * c[3]);
                rsloc[mt][0] += e0 + e1;
                rsloc[mt][1] += e2 + e3;
                uint32_t hp, lp;
                pack_split(e0, e1, hp, lp);
                size_t off = (size_t)z * zC + (size_t)r0 * N + ncol;
                *reinterpret_cast<uint32_t*>(o0h + off) = hp;
                *reinterpret_cast<uint32_t*>(o0l + off) = lp;
                pack_split(e2, e3, hp, lp);
                off += (size_t)8 * N;
                *reinterpret_cast<uint32_t*>(o0h + off) = hp;
                *reinterpret_cast<uint32_t*>(o0l + off) = lp;
            }
        }
        // reduce across the 4 lanes sharing each row
#pragma unroll
        for (int mt = 0; mt < 4; ++mt)
#pragma unroll
            for (int h = 0; h < 2; ++h) {
                float v = rsloc[mt][h];
                v += __shfl_xor_sync(0xffffffffu, v, 1);
                v += __shfl_xor_sync(0xffffffffu, v, 2);
                rsloc[mt][h] = v;
            }
        if ((lane & 3) == 0) {
#pragma unroll
            for (int mt = 0; mt < 4; ++mt) {
                const int lr = wm * 64 + mt * 16 + qrow;
                psum[wn * GBM + lr] = rsloc[mt][0];
                psum[wn * GBM + lr + 8] = rsloc[mt][1];
            }
        }
        __syncthreads();
        if (tid < GBM) {
            const float s = psum[tid] + psum[GBM + tid] + psum[2 * GBM + tid] + psum[3 * GBM + tid];
            part[((size_t)z * M + m0 + tid) * gridDim.x + blockIdx.x] = s;
        }
        return;
    }

#pragma unroll
    for (int mt = 0; mt < 4; ++mt) {
        const int r0 = m0 + wm * 64 + mt * 16 + qrow;
        float sc0 = alpha, sc1 = alpha;
        if (MODE == 2) {
            sc0 = alpha / __ldg(&rsum[(size_t)z * M + r0]);
            sc1 = alpha / __ldg(&rsum[(size_t)z * M + r0 + 8]);
        }
#pragma unroll
        for (int nt = 0; nt < 4; ++nt) {
            const int ncol = n0 + wn * 32 + nt * 8 + qcol;
            const float* c = acc[mt][nt];
            if (MODE == 2) {
                float* base = Cf + (size_t)z * zC;
                float2 v0 = make_float2(sc0 * c[0], sc0 * c[1]);
                float2 v1 = make_float2(sc1 * c[2], sc1 * c[3]);
                *reinterpret_cast<float2*>(base + (size_t)r0 * N + ncol) = v0;
                *reinterpret_cast<float2*>(base + (size_t)(r0 + 8) * N + ncol) = v1;
            } else {   // MODE 1
                const int sel = ncol >> 10;
                __nv_bfloat16* Dh = (sel == 0) ? o0h : ((sel == 1) ? o1h : o2h);
                __nv_bfloat16* Dl = (sel == 0) ? o0l : ((sel == 1) ? o1l : o2l);
                const int cm = ncol & (DD - 1);
                uint32_t hp, lp;
                pack_split(c[0], c[1], hp, lp);
                size_t off = (size_t)r0 * DD + cm;
                *reinterpret_cast<uint32_t*>(Dh + off) = hp;
                *reinterpret_cast<uint32_t*>(Dl + off) = lp;
                pack_split(c[2], c[3], hp, lp);
                off += (size_t)8 * DD;
                *reinterpret_cast<uint32_t*>(Dh + off) = hp;
                *reinterpret_cast<uint32_t*>(Dl + off) = lp;
            }
        }
    }
}

// ---------------- aux kernels ----------------
__global__ __launch_bounds__(256)
void split_f32(const float* __restrict__ in, __nv_bfloat16* __restrict__ hi,
               __nv_bfloat16* __restrict__ lo, size_t n4)
{
    size_t i = (size_t)blockIdx.x * 256 + threadIdx.x;
    if (i >= n4) return;
    float4 v = reinterpret_cast<const float4*>(in)[i];
    uint32_t h0, l0, h1, l1;
    pack_split(v.x, v.y, h0, l0);
    pack_split(v.z, v.w, h1, l1);
    reinterpret_cast<uint2*>(hi)[i] = make_uint2(h0, h1);
    reinterpret_cast<uint2*>(lo)[i] = make_uint2(l0, l1);
}

__global__ __launch_bounds__(256)
void split_w_t(const float* __restrict__ Wq, const float* __restrict__ Wk,
               const float* __restrict__ Wv,
               __nv_bfloat16* __restrict__ th, __nv_bfloat16* __restrict__ tl)
{
    __shared__ float tile[32][33];
    const int zz = blockIdx.z;
    const float* W = (zz == 0) ? Wq : ((zz == 1) ? Wk : Wv);
    const int k0 = blockIdx.x * 32;
    const int n0 = blockIdx.y * 32;
    const int lx = threadIdx.x & 31, ly = threadIdx.x >> 5;
#pragma unroll
    for (int i = 0; i < 32; i += 8)
        tile[ly + i][lx] = W[(size_t)(k0 + ly + i) * DD + n0 + lx];
    __syncthreads();
#pragma unroll
    for (int i = 0; i < 32; i += 8) {
        float v = tile[lx][ly + i];
        __nv_bfloat16 h = __float2bfloat16(v);
        __nv_bfloat16 l = __float2bfloat16(v - __bfloat162float(h));
        size_t o = ((size_t)zz * DD + (n0 + ly + i)) * DD + k0 + lx;
        th[o] = h;
        tl[o] = l;
    }
}

__global__ __launch_bounds__(256)
void transpose_v(const __nv_bfloat16* __restrict__ vh, const __nv_bfloat16* __restrict__ vl,
                 __nv_bfloat16* __restrict__ vth, __nv_bfloat16* __restrict__ vtl)
{
    __shared__ __nv_bfloat16 t0[32][33], t1[32][33];
    const int b = blockIdx.z;
    const int s0 = blockIdx.x * 32, d0 = blockIdx.y * 32;
    const int lx = threadIdx.x & 31, ly = threadIdx.x >> 5;
#pragma unroll
    for (int i = 0; i < 32; i += 8) {
        size_t src = ((size_t)b * SS + s0 + ly + i) * DD + d0 + lx;
        t0[ly + i][lx] = vh[src];
        t1[ly + i][lx] = vl[src];
    }
    __syncthreads();
#pragma unroll
    for (int i = 0; i < 32; i += 8) {
        size_t dst = (size_t)b * SS * DD + (size_t)(d0 + ly + i) * SS + s0 + lx;
        vth[dst] = t0[lx][ly + i];
        vtl[dst] = t1[lx][ly + i];
    }
}

// sum the 32 per-colTile partials for each row -> rsum
__global__ __launch_bounds__(256)
void reduce_rsum(const float* __restrict__ part, float* __restrict__ rsum)
{
    const int row = blockIdx.x * 8 + (threadIdx.x >> 5);
    const int lane = threadIdx.x & 31;
    float v = part[(size_t)row * 32 + lane];
#pragma unroll
    for (int o = 16; o > 0; o >>= 1) v += __shfl_xor_sync(0xffffffffu, v, o);
    if (lane == 0) rsum[row] = v;
}

// ---------------- launch ----------------
extern "C" void kernel_launch(void* const* d_in, const int* in_sizes, int n_in,
                              void* d_out, int out_size)
{
    const float* x  = (const float*)d_in[0];
    const float* Wq = (const float*)d_in[1];
    const float* Wk = (const float*)d_in[2];
    const float* Wv = (const float*)d_in[3];
    float* out = (float*)d_out;

    __nv_bfloat16 *pxh, *pxl, *pwth, *pwtl, *pqh, *pql, *pkh, *pkl, *pvh, *pvl, *pvth, *pvtl, *pph, *ppl;
    float *prs, *ppart;
    cudaGetSymbolAddress((void**)&pxh, g_xh);   cudaGetSymbolAddress((void**)&pxl, g_xl);
    cudaGetSymbolAddress((void**)&pwth, g_wth); cudaGetSymbolAddress((void**)&pwtl, g_wtl);
    cudaGetSymbolAddress((void**)&pqh, g_qh);   cudaGetSymbolAddress((void**)&pql, g_ql);
    cudaGetSymbolAddress((void**)&pkh, g_kh);   cudaGetSymbolAddress((void**)&pkl, g_kl);
    cudaGetSymbolAddress((void**)&pvh, g_vh);   cudaGetSymbolAddress((void**)&pvl, g_vl);
    cudaGetSymbolAddress((void**)&pvth, g_vth); cudaGetSymbolAddress((void**)&pvtl, g_vtl);
    cudaGetSymbolAddress((void**)&pph, g_ph);   cudaGetSymbolAddress((void**)&ppl, g_pl);
    cudaGetSymbolAddress((void**)&prs, g_rsum); cudaGetSymbolAddress((void**)&ppart, g_part);

    cudaFuncSetAttribute(tc_gemm<1>, cudaFuncAttributeMaxDynamicSharedMemorySize, GEMM_SMEM);
    cudaFuncSetAttribute(tc_gemm<2>, cudaFuncAttributeMaxDynamicSharedMemorySize, GEMM_SMEM);
    cudaFuncSetAttribute(tc_gemm<3>, cudaFuncAttributeMaxDynamicSharedMemorySize, GEMM_SMEM);

    // 1) split inputs
    split_f32<<<(unsigned)(((size_t)MPROJ * DD / 4 + 255) / 256), 256>>>(x, pxh, pxl, (size_t)MPROJ * DD / 4);
    split_w_t<<<dim3(DD / 32, DD / 32, 3), 256>>>(Wq, Wk, Wv, pwth, pwtl);

    // 2) fused QKV projection
    tc_gemm<1><<<dim3(3 * DD / GBN, MPROJ / GBM, 1), 256, GEMM_SMEM>>>(
        pxh, pxl, pwth, pwtl, nullptr,
        pqh, pql, pkh, pkl, pvh, pvl,
        MPROJ, 3 * DD, DD, DD, DD, 0, 0, 0, 1.0f, nullptr, nullptr);

    // 3) V transpose (per batch)
    transpose_v<<<dim3(SS / 32, DD / 32, BB), 256>>>(pvh, pvl, pvth, pvtl);

    // 4) QK^T + fused exp/split + row partial sums
    tc_gemm<3><<<dim3(SS / GBN, SS / GBM, BB), 256, GEMM_SMEM>>>(
        pqh, pql, pkh, pkl, nullptr,
        pph, ppl, nullptr, nullptr, nullptr, nullptr,
        SS, SS, DD, DD, DD,
        (size_t)SS * DD, (size_t)SS * DD, (size_t)SS * SS, 1.0f / 32.0f, nullptr, ppart);

    // 5) reduce partials -> rsum
    reduce_rsum<<<BB * SS / 8, 256>>>(ppart, prs);

    // 6) out = (P @ Vt^T) / rsum per batch
    tc_gemm<2><<<dim3(DD / GBN, SS / GBM, BB), 256, GEMM_SMEM>>>(
        pph, ppl, pvth, pvtl, out,
        nullptr, nullptr, nullptr, nullptr, nullptr, nullptr,
        SS, DD, SS, SS, SS,
        (size_t)SS * SS, (size_t)SS * DD, (size_t)SS * DD, 1.0f, prs, nullptr);
}